// round 12
// baseline (speedup 1.0000x reference)
#include <cuda_runtime.h>
#include <cuda_fp16.h>
#include <math.h>
#include <cstdint>

// ---------------- problem constants ----------------
#define B_GRAPHS 2048
#define F_NODES  64
#define D_IN     32
#define HDIM     128
#define HEADS    4
#define NC       16
#define EPG      128
#define N_NODES  (B_GRAPHS * F_NODES)        // 131072
#define E_EDGES  (B_GRAPHS * EPG)            // 262144

// ---------------- device-global scratch ----------------
__device__ uint2 g_w1pk[2 * 64 * 32];         // W1'=Wa@W1 B-frag fp16
__device__ float g_c1[512];                   // b_align @ W1
__device__ uint2 g_w2pk[32 * 16 * 32];        // W2^T B-frag fp16
__device__ uint4 g_embA_h[(size_t)8192 * 2 * 32];  // emb A-frag hi
__device__ uint4 g_embA_l[(size_t)8192 * 2 * 32];  // emb A-frag lo
__device__ float g_w1a[8 * 32];               // [sel*4+h][32] = Wa@(W1@a)
__device__ float g_c1a[8];                    // c1 · a

// ---------------- PTX helpers (sm_80+; no tcgen05 — ptxas targets compute_103) ----------------
__device__ __forceinline__ uint32_t smem_to_u32(const void* p) {
    uint32_t a;
    asm("{ .reg .u64 tmp; cvta.to.shared.u64 tmp, %1; cvt.u32.u64 %0, tmp; }" : "=r"(a) : "l"(p));
    return a;
}
#define LDSM_X4(r0, r1, r2, r3, addr) \
    asm volatile("ldmatrix.sync.aligned.m8n8.x4.shared.b16 {%0,%1,%2,%3}, [%4];" \
                 : "=r"(r0), "=r"(r1), "=r"(r2), "=r"(r3) : "r"(addr))
#define LDSM_X4T(r0, r1, r2, r3, addr) \
    asm volatile("ldmatrix.sync.aligned.m8n8.x4.trans.shared.b16 {%0,%1,%2,%3}, [%4];" \
                 : "=r"(r0), "=r"(r1), "=r"(r2), "=r"(r3) : "r"(addr))

#define MMAF16(d, a, b0, b1) \
    asm volatile("mma.sync.aligned.m16n8k16.row.col.f32.f16.f16.f32 " \
                 "{%0,%1,%2,%3}, {%4,%5,%6,%7}, {%8,%9}, {%0,%1,%2,%3};" \
                 : "+f"((d)[0]), "+f"((d)[1]), "+f"((d)[2]), "+f"((d)[3]) \
                 : "r"((a)[0]), "r"((a)[1]), "r"((a)[2]), "r"((a)[3]), "r"(b0), "r"(b1))

__device__ __forceinline__ uint32_t pack_h2(float a, float b) {
    __half2 v = __halves2half2(__float2half_rn(a), __float2half_rn(b));
    return *(uint32_t*)&v;
}
__device__ __forceinline__ void split_pair_h(float a, float b, uint32_t& hi, uint32_t& lo) {
    __half ha = __float2half_rn(a), hb = __float2half_rn(b);
    __half2 H = __halves2half2(ha, hb);
    __half2 L = __halves2half2(__float2half_rn(a - __half2float(ha)),
                               __float2half_rn(b - __half2float(hb)));
    hi = *(uint32_t*)&H;
    lo = *(uint32_t*)&L;
}

// ---------------- merged prep kernel ----------------
__global__ __launch_bounds__(256) void prep_kernel(
    const float* __restrict__ emb,
    const float* __restrict__ Wa, const float* __restrict__ W1,
    const float* __restrict__ W2, const float* __restrict__ b_align,
    const float* __restrict__ a_src1, const float* __restrict__ a_dst1,
    const float* __restrict__ gl, float* __restrict__ gate_out)
{
    int bid = blockIdx.x, t = threadIdx.x;
    if (bid < 2048) {
        int gid = bid * 256 + t;
        int lane = gid & 31;
        int ks = (gid >> 5) & 1;
        int grp = gid >> 6;
        int gr = lane >> 2, gc = (lane & 3) * 2;
        const float* base = emb + (size_t)grp * 16 * 32 + ks * 16;
        float2 p0 = *(const float2*)(base + gr * 32 + gc);
        float2 p1 = *(const float2*)(base + (gr + 8) * 32 + gc);
        float2 p2 = *(const float2*)(base + gr * 32 + gc + 8);
        float2 p3 = *(const float2*)(base + (gr + 8) * 32 + gc + 8);
        uint4 H, L;
        split_pair_h(p0.x, p0.y, H.x, L.x);
        split_pair_h(p1.x, p1.y, H.y, L.y);
        split_pair_h(p2.x, p2.y, H.z, L.z);
        split_pair_h(p3.x, p3.y, H.w, L.w);
        g_embA_h[gid] = H;
        g_embA_l[gid] = L;
    } else if (bid < 2211) {
        int gid = (bid - 2048) * 256 + t;
        if (gid < 8192) {
            int reg = gid & 1, lane = (gid >> 1) & 31, gnt = (gid >> 6) & 63, ks = gid >> 12;
            int n = gnt * 8 + (lane >> 2);
            int k = ks * 16 + reg * 8 + (lane & 3) * 2;
            float v0 = 0.f, v1 = 0.f;
#pragma unroll 8
            for (int m = 0; m < 128; m++) {
                v0 = fmaf(Wa[k * 128 + m], W1[m * 512 + n], v0);
                v1 = fmaf(Wa[(k + 1) * 128 + m], W1[m * 512 + n], v1);
            }
            ((uint32_t*)g_w1pk)[gid] = pack_h2(v0, v1);
        } else if (gid < 40960) {
            int wid = gid - 8192;
            int reg = wid & 1, lane = (wid >> 1) & 31, gnt = (wid >> 6) & 15, ks = wid >> 10;
            int n = gnt * 8 + (lane >> 2);
            int k = ks * 16 + reg * 8 + (lane & 3) * 2;
            ((uint32_t*)g_w2pk)[wid] = pack_h2(W2[k * 128 + n], W2[(k + 1) * 128 + n]);
        } else if (gid < 41472) {
            int n = gid - 40960;
            float acc = 0.f;
#pragma unroll 8
            for (int m = 0; m < 128; m++) acc = fmaf(b_align[m], W1[m * 512 + n], acc);
            g_c1[n] = acc;
        } else if (gid < 41536) {
            int f = gid - 41472;
            if (gate_out != nullptr) gate_out[f] = 1.0f / (1.0f + expf(-gl[f]));
        }
    } else {
        __shared__ float t1[8][128];
        for (int i = 0; i < 4; i++) {
            int e = t * 4 + i;
            int hs = e >> 7, m = e & 127;
            int h = hs & 3, sel = hs >> 2;
            const float* av = (sel ? a_dst1 : a_src1) + h * 128;
            float acc = 0.f;
#pragma unroll 8
            for (int nl = 0; nl < 128; nl++)
                acc = fmaf(W1[m * 512 + h * 128 + nl], av[nl], acc);
            t1[hs][m] = acc;
        }
        __syncthreads();
        {
            int hs = t >> 5, k = t & 31;
            float acc = 0.f;
#pragma unroll 8
            for (int m = 0; m < 128; m++) acc = fmaf(Wa[k * 128 + m], t1[hs][m], acc);
            g_w1a[t] = acc;
        }
        if (t < 8) {
            float acc = 0.f;
#pragma unroll 8
            for (int m = 0; m < 128; m++) acc = fmaf(b_align[m], t1[t][m], acc);
            g_c1a[t] = acc;
        }
    }
}

// ---------------- mega kernel (warp grid 2x4: wm in {0,1} x 32 rows, wn in {0..3} x 32 cols) ----------------
// dyn smem (51200 B, occ 3):
//  X [0,33792): loop = h1 fp16 [64][136] (17408) + alpha fp16 [64][72] @17408 (9216); post = h2 fp32 [64][132]
//  o1 fp16 [64][136] @33792 (17408)
#define MG_ALPHA 17408
#define MG_O1    33792
#define MG_DYN   51200

__global__ __launch_bounds__(256, 3) void mega_kernel(
    const int* __restrict__ eidx, const float* __restrict__ gl,
    const float* __restrict__ emb,
    const float* __restrict__ b1,
    const float* __restrict__ a_src2, const float* __restrict__ a_dst2,
    const float* __restrict__ b2,
    const float* __restrict__ Wc1, const float* __restrict__ bc1,
    const float* __restrict__ Wc2, const float* __restrict__ bc2,
    float* __restrict__ outp)
{
    extern __shared__ __align__(16) char smem[];
    __half* s_h1  = (__half*)smem;                       // stride 136 halves
    __half* s_al  = (__half*)(smem + MG_ALPHA);          // stride 72 halves
    float*  s_h2  = (float*)smem;                        // stride 132 (post-loop)
    __half* s_o1  = (__half*)(smem + MG_O1);             // stride 136 halves
    uint32_t sb    = smem_to_u32(smem);
    uint32_t sbAl  = sb + MG_ALPHA;
    uint32_t sbO1  = sb + MG_O1;

    __shared__ int   s_ed[192], s_esrc[192], s_startc[65], s_deg[64], s_cur[64];
    __shared__ float s_sc[2][4][64];
    __shared__ float s_aprob[4 * 192];
    __shared__ float s_s2[128];
    __shared__ float s_q[64], s_g[128], s_hc[64];

    int b = blockIdx.x, t = threadIdx.x, lane = t & 31, w = t >> 5;
    int wm = w >> 2, wn = w & 3;                         // 2 x 4
    int gr = lane >> 2, gc = (lane & 3) * 2;
    int node0 = b * 64;

    // ---------- phase 0 ----------
    if (t < 64) { s_deg[t] = 0; s_cur[t] = 0; s_q[t] = 0.f; }
    if (t >= 64 && t < 192) s_s2[t - 64] = 0.f;
    if (t < 192) {
        int src, tt;
        if (t < 128) { src = eidx[b * 128 + t] - node0; tt = eidx[E_EDGES + b * 128 + t] - node0; }
        else         { src = t - 128; tt = src; }
        s_ed[t] = src | (tt << 8);
    }
    {
        uint32_t* az = (uint32_t*)(smem + MG_ALPHA);
#pragma unroll
        for (int i = 0; i < 9; i++) az[t + i * 256] = 0u;
    }
    // GAT1 scores via precomputed 32-vectors
    {
        int row = t & 63, sel = (t >> 6) & 1, hp = t >> 7;
        const float4* erow = (const float4*)(emb + (size_t)(node0 + row) * 32);
        float4 e0 = __ldg(erow), e1 = __ldg(erow + 1), e2 = __ldg(erow + 2), e3 = __ldg(erow + 3);
        float4 e4 = __ldg(erow + 4), e5 = __ldg(erow + 5), e6 = __ldg(erow + 6), e7 = __ldg(erow + 7);
        float gate = 1.0f / (1.0f + __expf(-__ldg(&gl[row])));
#pragma unroll
        for (int hh = 0; hh < 2; hh++) {
            int h = hp * 2 + hh, hs = sel * 4 + h;
            const float4* wv = (const float4*)(g_w1a + hs * 32);
            float s = __ldg(&g_c1a[hs]);
            float4 w0 = __ldg(wv), w1v = __ldg(wv + 1), w2v = __ldg(wv + 2), w3v = __ldg(wv + 3);
            float4 w4 = __ldg(wv + 4), w5 = __ldg(wv + 5), w6 = __ldg(wv + 6), w7 = __ldg(wv + 7);
            s += e0.x*w0.x + e0.y*w0.y + e0.z*w0.z + e0.w*w0.w;
            s += e1.x*w1v.x + e1.y*w1v.y + e1.z*w1v.z + e1.w*w1v.w;
            s += e2.x*w2v.x + e2.y*w2v.y + e2.z*w2v.z + e2.w*w2v.w;
            s += e3.x*w3v.x + e3.y*w3v.y + e3.z*w3v.z + e3.w*w3v.w;
            s += e4.x*w4.x + e4.y*w4.y + e4.z*w4.z + e4.w*w4.w;
            s += e5.x*w5.x + e5.y*w5.y + e5.z*w5.z + e5.w*w5.w;
            s += e6.x*w6.x + e6.y*w6.y + e6.z*w6.z + e6.w*w6.w;
            s += e7.x*w7.x + e7.y*w7.y + e7.z*w7.z + e7.w*w7.w;
            s_sc[sel][h][row] = gate * s;
        }
    }
    // gates for this thread's 4 output rows
    float gate_r[2][2];
#pragma unroll
    for (int mt = 0; mt < 2; mt++) {
        int r = wm * 32 + mt * 16 + gr;
        gate_r[mt][0] = 1.0f / (1.0f + __expf(-__ldg(&gl[r])));
        gate_r[mt][1] = 1.0f / (1.0f + __expf(-__ldg(&gl[r + 8])));
    }
    __syncthreads();
    if (t < 192) atomicAdd(&s_deg[s_ed[t] >> 8], 1);
    __syncthreads();
    if (w == 0) {
        int v0 = s_deg[lane * 2], v1 = s_deg[lane * 2 + 1];
        int p = v0 + v1, run = p;
#pragma unroll
        for (int off = 1; off < 32; off <<= 1) {
            int n = __shfl_up_sync(0xffffffffu, run, off);
            if (lane >= off) run += n;
        }
        s_startc[lane * 2] = run - p;
        s_startc[lane * 2 + 1] = run - p + v0;
        if (lane == 31) s_startc[64] = run;
    }
    __syncthreads();
    if (t < 192) {
        int tt = s_ed[t] >> 8, src = s_ed[t] & 255;
        int pos = atomicAdd(&s_cur[tt], 1);
        s_esrc[s_startc[tt] + pos] = src;
    }
    __syncthreads();

    // ---------- GAT1 softmax, all heads ----------
    {
        int h = t >> 6, tt = t & 63;
        int k0 = s_startc[tt], k1 = s_startc[tt + 1];
        float sd = s_sc[1][h][tt];
        float* ap = s_aprob + h * 192;
        float mx = -1e30f;
        for (int k = k0; k < k1; k++) {
            float sc = s_sc[0][h][s_esrc[k]] + sd;
            sc = sc > 0.f ? sc : 0.2f * sc;
            ap[k] = sc;
            mx = fmaxf(mx, sc);
        }
        float sum = 0.f;
        for (int k = k0; k < k1; k++) {
            float p = __expf(ap[k] - mx);
            ap[k] = p;
            sum += p;
        }
        float inv = 1.f / (sum + 1e-16f);
        for (int k = k0; k < k1; k++) ap[k] *= inv;
    }
    __syncthreads();

    float acc2[2][4][4] = {};                            // persistent GEMM2 accumulator

    // ---------- head loop ----------
    for (int h = 0; h < HEADS; h++) {
        int hoff = h * 128;

        // GEMM1: rows wm*32+mt*16, cols wn*32 (4 n-tiles)
        float acc1[2][4][4] = {};
#pragma unroll
        for (int mt = 0; mt < 2; mt++) {
            int grp = b * 4 + wm * 2 + mt;
#pragma unroll
            for (int ks = 0; ks < 2; ks++) {
                uint4 H4 = __ldg(&g_embA_h[(size_t)(grp * 2 + ks) * 32 + lane]);
                uint4 L4 = __ldg(&g_embA_l[(size_t)(grp * 2 + ks) * 32 + lane]);
                uint32_t Ah[4] = { H4.x, H4.y, H4.z, H4.w };
                uint32_t Al[4] = { L4.x, L4.y, L4.z, L4.w };
                int base = (ks * 64 + h * 16 + wn * 4) * 32 + lane;
#pragma unroll
                for (int i = 0; i < 4; i++) {
                    uint2 bw = __ldg(&g_w1pk[base + i * 32]);
                    MMAF16(acc1[mt][i], Ah, bw.x, bw.y);
                    MMAF16(acc1[mt][i], Al, bw.x, bw.y);
                }
            }
        }
        // epilogue: h1 fp16
#pragma unroll
        for (int mt = 0; mt < 2; mt++) {
            int r = wm * 32 + mt * 16 + gr;
#pragma unroll
            for (int i = 0; i < 4; i++) {
                int col = wn * 32 + i * 8 + gc;
                float c0 = __ldg(&g_c1[hoff + col]), c1v = __ldg(&g_c1[hoff + col + 1]);
                *(uint32_t*)(s_h1 + r * 136 + col) =
                    pack_h2(gate_r[mt][0] * (acc1[mt][i][0] + c0),
                            gate_r[mt][0] * (acc1[mt][i][1] + c1v));
                *(uint32_t*)(s_h1 + (r + 8) * 136 + col) =
                    pack_h2(gate_r[mt][1] * (acc1[mt][i][2] + c0),
                            gate_r[mt][1] * (acc1[mt][i][3] + c1v));
            }
        }
        // alpha build (thread-per-target)
        if (t < 64) {
            int tt = t;
            int k0 = s_startc[tt], k1 = s_startc[tt + 1];
            const float* ap = s_aprob + h * 192;
            __half* row = s_al + tt * 72;
            for (int k = k0; k < k1; k++) row[s_esrc[k]] = __float2half_rn(0.f);
            for (int k = k0; k < k1; k++) {
                int s = s_esrc[k];
                row[s] = __float2half_rn(__half2float(row[s]) + ap[k]);
            }
        }
        __syncthreads();                                 // S1

        // agg MMA: o1 = alpha @ h1; warp: rows wm*32 (2 mt), cols wn*32 (2 n16 pairs)
        {
            float ag[2][4][4] = {};
#pragma unroll
            for (int ks = 0; ks < 4; ks++) {
                uint32_t A0[4], A1[4], B0[4], B1[4];
                uint32_t aBase = sbAl + (uint32_t)((wm * 32 + (lane & 15)) * 144
                                                   + (lane >> 4) * 16 + ks * 32);
                LDSM_X4(A0[0], A0[1], A0[2], A0[3], aBase);
                LDSM_X4(A1[0], A1[1], A1[2], A1[3], aBase + 16 * 144);
                uint32_t bBase = sb + (uint32_t)((lane & 15) * 272
                                                 + (wn * 32 + (lane >> 4) * 8) * 2 + ks * 4352);
                LDSM_X4T(B0[0], B0[1], B0[2], B0[3], bBase);
                LDSM_X4T(B1[0], B1[1], B1[2], B1[3], bBase + 32);
                MMAF16(ag[0][0], A0, B0[0], B0[1]);
                MMAF16(ag[0][1], A0, B0[2], B0[3]);
                MMAF16(ag[0][2], A0, B1[0], B1[1]);
                MMAF16(ag[0][3], A0, B1[2], B1[3]);
                MMAF16(ag[1][0], A1, B0[0], B0[1]);
                MMAF16(ag[1][1], A1, B0[2], B0[3]);
                MMAF16(ag[1][2], A1, B1[0], B1[1]);
                MMAF16(ag[1][3], A1, B1[2], B1[3]);
            }
            // epi: + b1, elu, fp16 -> o1
#pragma unroll
            for (int mt = 0; mt < 2; mt++) {
                int r = wm * 32 + mt * 16 + gr;
#pragma unroll
                for (int nt = 0; nt < 4; nt++) {
                    int col = wn * 32 + nt * 8 + gc;
                    float b0v = __ldg(&b1[hoff + col]), b1v = __ldg(&b1[hoff + col + 1]);
                    float vx = ag[mt][nt][0] + b0v, vy = ag[mt][nt][1] + b1v;
                    float vz = ag[mt][nt][2] + b0v, vw = ag[mt][nt][3] + b1v;
                    vx = vx > 0.f ? vx : (__expf(vx) - 1.f);
                    vy = vy > 0.f ? vy : (__expf(vy) - 1.f);
                    vz = vz > 0.f ? vz : (__expf(vz) - 1.f);
                    vw = vw > 0.f ? vw : (__expf(vw) - 1.f);
                    *(uint32_t*)(s_o1 + r * 136 + col) = pack_h2(vx, vy);
                    *(uint32_t*)(s_o1 + (r + 8) * 136 + col) = pack_h2(vz, vw);
                }
            }
        }
        __syncthreads();                                 // S2

        // GEMM2 partial: acc2 += o1_head @ W2[head]; warp: 2 mt x 4 gnt, all k
        {
#pragma unroll
            for (int kk = 0; kk < 8; kk++) {
                uint32_t A0[4], A1[4];
                uint32_t aBase = sbO1 + (uint32_t)((wm * 32 + (lane & 15)) * 272
                                                   + (lane >> 4) * 16 + kk * 32);
                LDSM_X4(A0[0], A0[1], A0[2], A0[3], aBase);
                LDSM_X4(A1[0], A1[1], A1[2], A1[3], aBase + 16 * 272);
                int base = ((h * 8 + kk) * 16 + wn * 4) * 32 + lane;
#pragma unroll
                for (int i = 0; i < 4; i++) {
                    uint2 bw = __ldg(&g_w2pk[base + i * 32]);
                    MMAF16(acc2[0][i], A0, bw.x, bw.y);
                    MMAF16(acc2[1][i], A1, bw.x, bw.y);
                }
            }
        }
    }

    // ---------- h2 write + GAT2 score partials ----------
    {
#pragma unroll
        for (int mt = 0; mt < 2; mt++) {
            int r = wm * 32 + mt * 16 + gr;
            float p1s = 0.f, p1d = 0.f, p2s = 0.f, p2d = 0.f;
#pragma unroll
            for (int i = 0; i < 4; i++) {
                int col = wn * 32 + i * 8 + gc;
                s_h2[r * 132 + col]           = acc2[mt][i][0];
                s_h2[r * 132 + col + 1]       = acc2[mt][i][1];
                s_h2[(r + 8) * 132 + col]     = acc2[mt][i][2];
                s_h2[(r + 8) * 132 + col + 1] = acc2[mt][i][3];
                float as0 = __ldg(&a_src2[col]), as1 = __ldg(&a_src2[col + 1]);
                float ad0 = __ldg(&a_dst2[col]), ad1 = __ldg(&a_dst2[col + 1]);
                p1s += acc2[mt][i][0] * as0 + acc2[mt][i][1] * as1;
                p1d += acc2[mt][i][0] * ad0 + acc2[mt][i][1] * ad1;
                p2s += acc2[mt][i][2] * as0 + acc2[mt][i][3] * as1;
                p2d += acc2[mt][i][2] * ad0 + acc2[mt][i][3] * ad1;
            }
            atomicAdd(&s_s2[r], p1s);
            atomicAdd(&s_s2[64 + r], p1d);
            atomicAdd(&s_s2[r + 8], p2s);
            atomicAdd(&s_s2[64 + r + 8], p2d);
        }
    }
    __syncthreads();

    // ---------- GAT2 softmax ----------
    if (t < 64) {
        int tt = t;
        int k0 = s_startc[tt], k1 = s_startc[tt + 1];
        float sd = s_s2[64 + tt];
        float mx = -1e30f;
        for (int k = k0; k < k1; k++) {
            float sc = s_s2[s_esrc[k]] + sd;
            sc = sc > 0.f ? sc : 0.2f * sc;
            s_aprob[k] = sc;
            mx = fmaxf(mx, sc);
        }
        float sum = 0.f;
        for (int k = k0; k < k1; k++) {
            float p = __expf(s_aprob[k] - mx);
            s_aprob[k] = p;
            sum += p;
        }
        float inv = 1.f / (sum + 1e-16f);
        for (int k = k0; k < k1; k++) s_aprob[k] *= inv;
    }
    __syncthreads();

    // ---------- pooled GAT2 ----------
    if (t < 192) atomicAdd(&s_q[s_esrc[t]], s_aprob[t]);
    __syncthreads();
    if (t < 128) {
        float a = 0.f;
#pragma unroll 8
        for (int src = 0; src < 64; src++)
            a = fmaf(s_q[src], s_h2[src * 132 + t], a);
        s_g[t] = a * (1.0f / 64.0f) + __ldg(&b2[t]);
    }
    __syncthreads();

    // ---------- classifier ----------
    if (t < 64) {
        float a = __ldg(&bc1[t]);
#pragma unroll 8
        for (int d = 0; d < 128; d++) a = fmaf(s_g[d], __ldg(&Wc1[d * 64 + t]), a);
        s_hc[t] = a > 0.f ? a : 0.01f * a;
    }
    __syncthreads();
    if (t < 16) {
        float a = __ldg(&bc2[t]);
#pragma unroll 8
        for (int j = 0; j < 64; j++) a = fmaf(s_hc[j], __ldg(&Wc2[j * 16 + t]), a);
        outp[(size_t)b * 16 + t] = a;
    }
}

// ---------------- launch ----------------
extern "C" void kernel_launch(void* const* d_in, const int* in_sizes, int n_in,
                              void* d_out, int out_size)
{
    const float* emb         = (const float*)d_in[0];
    const int*   edge_index  = (const int*)d_in[1];
    const float* W_align     = (const float*)d_in[3];
    const float* b_align     = (const float*)d_in[4];
    const float* gate_logits = (const float*)d_in[5];
    const float* W1          = (const float*)d_in[6];
    const float* a_src1      = (const float*)d_in[7];
    const float* a_dst1      = (const float*)d_in[8];
    const float* b1          = (const float*)d_in[9];
    const float* W2          = (const float*)d_in[10];
    const float* a_src2      = (const float*)d_in[11];
    const float* a_dst2      = (const float*)d_in[12];
    const float* b2          = (const float*)d_in[13];
    const float* Wc1         = (const float*)d_in[14];
    const float* bc1         = (const float*)d_in[15];
    const float* Wc2         = (const float*)d_in[16];
    const float* bc2         = (const float*)d_in[17];
    float* out = (float*)d_out;

    cudaFuncSetAttribute(mega_kernel, cudaFuncAttributeMaxDynamicSharedMemorySize, MG_DYN);

    float* gate_out = (out_size >= 64) ? (out + (out_size - 64)) : nullptr;

    prep_kernel<<<2212, 256>>>(emb, W_align, W1, W2, b_align,
                               a_src1, a_dst1, gate_logits, gate_out);

    mega_kernel<<<B_GRAPHS, 256, MG_DYN>>>(
        edge_index, gate_logits, emb,
        b1, a_src2, a_dst2, b2,
        Wc1, bc1, Wc2, bc2, out);
}

// round 13
// speedup vs baseline: 1.0734x; 1.0734x over previous
#include <cuda_runtime.h>
#include <cuda_fp16.h>
#include <math.h>
#include <cstdint>

// ---------------- problem constants ----------------
#define B_GRAPHS 2048
#define F_NODES  64
#define D_IN     32
#define HDIM     128
#define HEADS    4
#define NC       16
#define EPG      128
#define N_NODES  (B_GRAPHS * F_NODES)        // 131072
#define E_EDGES  (B_GRAPHS * EPG)            // 262144

// ---------------- device-global scratch ----------------
__device__ uint2 g_w1pk[2 * 64 * 32];         // W1'=Wa@W1 B-frag fp16
__device__ float g_c1[512];                   // b_align @ W1
__device__ uint2 g_w2pk[32 * 16 * 32];        // W2^T B-frag fp16
__device__ float g_w1a[8 * 32];               // [sel*4+h][32] = Wa@(W1@a)
__device__ float g_c1a[8];                    // c1 · a

// ---------------- PTX helpers (sm_80+; no tcgen05 — ptxas targets compute_103) ----------------
__device__ __forceinline__ uint32_t smem_to_u32(const void* p) {
    uint32_t a;
    asm("{ .reg .u64 tmp; cvta.to.shared.u64 tmp, %1; cvt.u32.u64 %0, tmp; }" : "=r"(a) : "l"(p));
    return a;
}
#define LDSM_X4(r0, r1, r2, r3, addr) \
    asm volatile("ldmatrix.sync.aligned.m8n8.x4.shared.b16 {%0,%1,%2,%3}, [%4];" \
                 : "=r"(r0), "=r"(r1), "=r"(r2), "=r"(r3) : "r"(addr))
#define LDSM_X4T(r0, r1, r2, r3, addr) \
    asm volatile("ldmatrix.sync.aligned.m8n8.x4.trans.shared.b16 {%0,%1,%2,%3}, [%4];" \
                 : "=r"(r0), "=r"(r1), "=r"(r2), "=r"(r3) : "r"(addr))

#define MMAF16(d, a, b0, b1) \
    asm volatile("mma.sync.aligned.m16n8k16.row.col.f32.f16.f16.f32 " \
                 "{%0,%1,%2,%3}, {%4,%5,%6,%7}, {%8,%9}, {%0,%1,%2,%3};" \
                 : "+f"((d)[0]), "+f"((d)[1]), "+f"((d)[2]), "+f"((d)[3]) \
                 : "r"((a)[0]), "r"((a)[1]), "r"((a)[2]), "r"((a)[3]), "r"(b0), "r"(b1))

__device__ __forceinline__ uint32_t pack_h2(float a, float b) {
    __half2 v = __halves2half2(__float2half_rn(a), __float2half_rn(b));
    return *(uint32_t*)&v;
}
__device__ __forceinline__ void split_pair_h(float a, float b, uint32_t& hi, uint32_t& lo) {
    __half ha = __float2half_rn(a), hb = __float2half_rn(b);
    __half2 H = __halves2half2(ha, hb);
    __half2 L = __halves2half2(__float2half_rn(a - __half2float(ha)),
                               __float2half_rn(b - __half2float(hb)));
    hi = *(uint32_t*)&H;
    lo = *(uint32_t*)&L;
}

// ---------------- prep kernel (weights only; emb staged in mega now) ----------------
// blocks [0,163): weight frags + c1 + gate | block 163: score vectors
__global__ __launch_bounds__(256) void prep_kernel(
    const float* __restrict__ Wa, const float* __restrict__ W1,
    const float* __restrict__ W2, const float* __restrict__ b_align,
    const float* __restrict__ a_src1, const float* __restrict__ a_dst1,
    const float* __restrict__ gl, float* __restrict__ gate_out)
{
    int bid = blockIdx.x, t = threadIdx.x;
    if (bid < 163) {
        int gid = bid * 256 + t;
        if (gid < 8192) {
            int reg = gid & 1, lane = (gid >> 1) & 31, gnt = (gid >> 6) & 63, ks = gid >> 12;
            int n = gnt * 8 + (lane >> 2);
            int k = ks * 16 + reg * 8 + (lane & 3) * 2;
            float v0 = 0.f, v1 = 0.f;
#pragma unroll 8
            for (int m = 0; m < 128; m++) {
                v0 = fmaf(Wa[k * 128 + m], W1[m * 512 + n], v0);
                v1 = fmaf(Wa[(k + 1) * 128 + m], W1[m * 512 + n], v1);
            }
            ((uint32_t*)g_w1pk)[gid] = pack_h2(v0, v1);
        } else if (gid < 40960) {
            int wid = gid - 8192;
            int reg = wid & 1, lane = (wid >> 1) & 31, gnt = (wid >> 6) & 15, ks = wid >> 10;
            int n = gnt * 8 + (lane >> 2);
            int k = ks * 16 + reg * 8 + (lane & 3) * 2;
            ((uint32_t*)g_w2pk)[wid] = pack_h2(W2[k * 128 + n], W2[(k + 1) * 128 + n]);
        } else if (gid < 41472) {
            int n = gid - 40960;
            float acc = 0.f;
#pragma unroll 8
            for (int m = 0; m < 128; m++) acc = fmaf(b_align[m], W1[m * 512 + n], acc);
            g_c1[n] = acc;
        } else if (gid < 41536) {
            int f = gid - 41472;
            if (gate_out != nullptr) gate_out[f] = 1.0f / (1.0f + expf(-gl[f]));
        }
    } else {
        __shared__ float t1[8][128];
        for (int i = 0; i < 4; i++) {
            int e = t * 4 + i;
            int hs = e >> 7, m = e & 127;
            int h = hs & 3, sel = hs >> 2;
            const float* av = (sel ? a_dst1 : a_src1) + h * 128;
            float acc = 0.f;
#pragma unroll 8
            for (int nl = 0; nl < 128; nl++)
                acc = fmaf(W1[m * 512 + h * 128 + nl], av[nl], acc);
            t1[hs][m] = acc;
        }
        __syncthreads();
        {
            int hs = t >> 5, k = t & 31;
            float acc = 0.f;
#pragma unroll 8
            for (int m = 0; m < 128; m++) acc = fmaf(Wa[k * 128 + m], t1[hs][m], acc);
            g_w1a[t] = acc;
        }
        if (t < 8) {
            float acc = 0.f;
#pragma unroll 8
            for (int m = 0; m < 128; m++) acc = fmaf(b_align[m], t1[t][m], acc);
            g_c1a[t] = acc;
        }
    }
}

// ---------------- mega kernel (R11 layout: warp grid 4x2) ----------------
// dyn smem (61440 B, occ 3):
//  X [0,33792): loop = h1 fp16 [64][136] (17408) + alpha fp16 [64][72] @17408 (9216); post = h2 fp32 [64][132]
//  o1 fp16 [64][136] @33792 (17408)
//  emb stage hi/lo fp16 [64][40] each @51200/@56320 (10240) — written once, never overwritten
#define MG_ALPHA 17408
#define MG_O1    33792
#define MG_EMB   51200
#define MG_DYN   61440

__global__ __launch_bounds__(256, 3) void mega_kernel(
    const int* __restrict__ eidx, const float* __restrict__ gl,
    const float* __restrict__ emb,
    const float* __restrict__ b1,
    const float* __restrict__ a_src2, const float* __restrict__ a_dst2,
    const float* __restrict__ b2,
    const float* __restrict__ Wc1, const float* __restrict__ bc1,
    const float* __restrict__ Wc2, const float* __restrict__ bc2,
    float* __restrict__ outp)
{
    extern __shared__ __align__(16) char smem[];
    __half* s_h1  = (__half*)smem;                       // stride 136 halves
    __half* s_al  = (__half*)(smem + MG_ALPHA);          // stride 72 halves
    float*  s_h2  = (float*)smem;                        // stride 132 (post-loop)
    __half* s_o1  = (__half*)(smem + MG_O1);             // stride 136 halves
    uint32_t sb    = smem_to_u32(smem);
    uint32_t sbAl  = sb + MG_ALPHA;
    uint32_t sbO1  = sb + MG_O1;
    uint32_t sbEmb = sb + MG_EMB;

    __shared__ int   s_ed[192], s_esrc[192], s_startc[65], s_deg[64], s_cur[64];
    __shared__ float s_sc[2][4][64];                     // GAT1 [sel][head][row]
    __shared__ float s_aprob[4 * 192];
    __shared__ float s_s2[128];                          // GAT2 scores: [0,64) src, [64,128) dst
    __shared__ float s_q[64], s_g[128], s_hc[64];

    int b = blockIdx.x, t = threadIdx.x, lane = t & 31, w = t >> 5;
    int wm = w >> 1, wn = w & 1;                         // 4 x 2 (R11 layout)
    int gr = lane >> 2, gc = (lane & 3) * 2;
    int node0 = b * 64;
    int r0 = wm * 16 + gr;

    // ---------- phase 0 ----------
    if (t < 64) { s_deg[t] = 0; s_cur[t] = 0; s_q[t] = 0.f; }
    if (t >= 64 && t < 192) s_s2[t - 64] = 0.f;
    if (t < 192) {
        int src, tt;
        if (t < 128) { src = eidx[b * 128 + t] - node0; tt = eidx[E_EDGES + b * 128 + t] - node0; }
        else         { src = t - 128; tt = src; }
        s_ed[t] = src | (tt << 8);
    }
    // zero alpha region (2304 words)
    {
        uint32_t* az = (uint32_t*)(smem + MG_ALPHA);
#pragma unroll
        for (int i = 0; i < 9; i++) az[t + i * 256] = 0u;
    }
    // stage emb as hi/lo fp16 (80 B rows) — 1024 float2s, 4 per thread
    {
        __half* eh = (__half*)(smem + MG_EMB);
        __half* el = eh + 64 * 40;
#pragma unroll
        for (int i = 0; i < 4; i++) {
            int f = t * 4 + i;                           // 0..1023
            int row = f >> 4, p = f & 15;                // 16 float2 per row
            float2 v = *(const float2*)(emb + (size_t)(node0 + row) * 32 + p * 2);
            uint32_t hi, lo;
            split_pair_h(v.x, v.y, hi, lo);
            *(uint32_t*)(eh + row * 40 + p * 2) = hi;
            *(uint32_t*)(el + row * 40 + p * 2) = lo;
        }
    }
    // GAT1 scores via precomputed 32-vectors
    {
        int row = t & 63, sel = (t >> 6) & 1, hp = t >> 7;
        const float4* erow = (const float4*)(emb + (size_t)(node0 + row) * 32);
        float4 e0 = __ldg(erow), e1 = __ldg(erow + 1), e2 = __ldg(erow + 2), e3 = __ldg(erow + 3);
        float4 e4 = __ldg(erow + 4), e5 = __ldg(erow + 5), e6 = __ldg(erow + 6), e7 = __ldg(erow + 7);
        float gate = 1.0f / (1.0f + __expf(-__ldg(&gl[row])));
#pragma unroll
        for (int hh = 0; hh < 2; hh++) {
            int h = hp * 2 + hh, hs = sel * 4 + h;
            const float4* wv = (const float4*)(g_w1a + hs * 32);
            float s = __ldg(&g_c1a[hs]);
            float4 w0 = __ldg(wv), w1v = __ldg(wv + 1), w2v = __ldg(wv + 2), w3v = __ldg(wv + 3);
            float4 w4 = __ldg(wv + 4), w5 = __ldg(wv + 5), w6 = __ldg(wv + 6), w7 = __ldg(wv + 7);
            s += e0.x*w0.x + e0.y*w0.y + e0.z*w0.z + e0.w*w0.w;
            s += e1.x*w1v.x + e1.y*w1v.y + e1.z*w1v.z + e1.w*w1v.w;
            s += e2.x*w2v.x + e2.y*w2v.y + e2.z*w2v.z + e2.w*w2v.w;
            s += e3.x*w3v.x + e3.y*w3v.y + e3.z*w3v.z + e3.w*w3v.w;
            s += e4.x*w4.x + e4.y*w4.y + e4.z*w4.z + e4.w*w4.w;
            s += e5.x*w5.x + e5.y*w5.y + e5.z*w5.z + e5.w*w5.w;
            s += e6.x*w6.x + e6.y*w6.y + e6.z*w6.z + e6.w*w6.w;
            s += e7.x*w7.x + e7.y*w7.y + e7.z*w7.z + e7.w*w7.w;
            s_sc[sel][h][row] = gate * s;
        }
    }
    float gate0 = 1.0f / (1.0f + __expf(-__ldg(&gl[r0])));
    float gate1 = 1.0f / (1.0f + __expf(-__ldg(&gl[r0 + 8])));
    __syncthreads();
    if (t < 192) atomicAdd(&s_deg[s_ed[t] >> 8], 1);
    __syncthreads();
    if (w == 0) {
        int v0 = s_deg[lane * 2], v1 = s_deg[lane * 2 + 1];
        int p = v0 + v1, run = p;
#pragma unroll
        for (int off = 1; off < 32; off <<= 1) {
            int n = __shfl_up_sync(0xffffffffu, run, off);
            if (lane >= off) run += n;
        }
        s_startc[lane * 2] = run - p;
        s_startc[lane * 2 + 1] = run - p + v0;
        if (lane == 31) s_startc[64] = run;
    }
    __syncthreads();
    if (t < 192) {
        int tt = s_ed[t] >> 8, src = s_ed[t] & 255;
        int pos = atomicAdd(&s_cur[tt], 1);
        s_esrc[s_startc[tt] + pos] = src;
    }
    __syncthreads();

    // ---------- GAT1 softmax, all 4 heads (serial per target) ----------
    {
        int h = t >> 6, tt = t & 63;
        int k0 = s_startc[tt], k1 = s_startc[tt + 1];
        float sd = s_sc[1][h][tt];
        float* ap = s_aprob + h * 192;
        float mx = -1e30f;
        for (int k = k0; k < k1; k++) {
            float sc = s_sc[0][h][s_esrc[k]] + sd;
            sc = sc > 0.f ? sc : 0.2f * sc;
            ap[k] = sc;
            mx = fmaxf(mx, sc);
        }
        float sum = 0.f;
        for (int k = k0; k < k1; k++) {
            float p = __expf(ap[k] - mx);
            ap[k] = p;
            sum += p;
        }
        float inv = 1.f / (sum + 1e-16f);
        for (int k = k0; k < k1; k++) ap[k] *= inv;
    }
    __syncthreads();

    float acc2[8][4] = {};                               // persistent GEMM2 accumulator

    // ---------- head loop: [GEMM1 + h1 fp16 + alpha build] S1 [agg MMA -> o1] S2 [GEMM2] ----------
    uint32_t aEmbH = sbEmb + (uint32_t)((wm * 16 + (lane & 15)) * 80 + (lane >> 4) * 16);
    uint32_t aEmbL = aEmbH + 5120;

    for (int h = 0; h < HEADS; h++) {
        int hoff = h * 128;

        float acc1[8][4] = {};
#pragma unroll
        for (int ks = 0; ks < 2; ks++) {
            uint32_t Ah[4], Al[4];
            LDSM_X4(Ah[0], Ah[1], Ah[2], Ah[3], aEmbH + ks * 32);
            LDSM_X4(Al[0], Al[1], Al[2], Al[3], aEmbL + ks * 32);
            int base = (ks * 64 + h * 16 + wn * 8) * 32 + lane;
#pragma unroll
            for (int i = 0; i < 8; i++) {
                uint2 bw = __ldg(&g_w1pk[base + i * 32]);
                MMAF16(acc1[i], Ah, bw.x, bw.y);
                MMAF16(acc1[i], Al, bw.x, bw.y);
            }
        }
        // epilogue: h1 = gate*(acc + c1) -> fp16 smem
#pragma unroll
        for (int i = 0; i < 8; i++) {
            int col = wn * 64 + i * 8 + gc;
            float c0 = __ldg(&g_c1[hoff + col]), c1v = __ldg(&g_c1[hoff + col + 1]);
            *(uint32_t*)(s_h1 + r0 * 136 + col) =
                pack_h2(gate0 * (acc1[i][0] + c0), gate0 * (acc1[i][1] + c1v));
            *(uint32_t*)(s_h1 + (r0 + 8) * 136 + col) =
                pack_h2(gate1 * (acc1[i][2] + c0), gate1 * (acc1[i][3] + c1v));
        }
        // alpha build: thread-per-target, zero touched then accumulate (handles dup edges)
        if (t < 64) {
            int tt = t;
            int k0 = s_startc[tt], k1 = s_startc[tt + 1];
            const float* ap = s_aprob + h * 192;
            __half* row = s_al + tt * 72;
            for (int k = k0; k < k1; k++) row[s_esrc[k]] = __float2half_rn(0.f);
            for (int k = k0; k < k1; k++) {
                int s = s_esrc[k];
                row[s] = __float2half_rn(__half2float(row[s]) + ap[k]);
            }
        }
        __syncthreads();                                 // S1: h1 + alpha visible

        // agg MMA: o1 = alpha @ h1 (M=64, K=64, N=128), warp: rows wm*16, cols wn*64 (2 halves)
        {
            uint32_t aAddr = sbAl + (uint32_t)((wm * 16 + (lane & 15)) * 144 + (lane >> 4) * 16);
#pragma unroll
            for (int nh = 0; nh < 2; nh++) {
                int n0 = wn * 64 + nh * 32;
                uint32_t bAddr = sb + (uint32_t)((lane & 15) * 272 + (n0 + (lane >> 4) * 8) * 2);
                float ag[4][4] = {};
#pragma unroll
                for (int ks = 0; ks < 4; ks++) {
                    uint32_t A[4], B0[4], B1[4];
                    LDSM_X4(A[0], A[1], A[2], A[3], aAddr + ks * 32);
                    LDSM_X4T(B0[0], B0[1], B0[2], B0[3], bAddr + ks * 4352);
                    LDSM_X4T(B1[0], B1[1], B1[2], B1[3], bAddr + 32 + ks * 4352);
                    MMAF16(ag[0], A, B0[0], B0[1]);
                    MMAF16(ag[1], A, B0[2], B0[3]);
                    MMAF16(ag[2], A, B1[0], B1[1]);
                    MMAF16(ag[3], A, B1[2], B1[3]);
                }
#pragma unroll
                for (int nt = 0; nt < 4; nt++) {
                    int col = n0 + nt * 8 + gc;
                    float b0v = __ldg(&b1[hoff + col]), b1v = __ldg(&b1[hoff + col + 1]);
                    float vx = ag[nt][0] + b0v, vy = ag[nt][1] + b1v;
                    float vz = ag[nt][2] + b0v, vw = ag[nt][3] + b1v;
                    vx = vx > 0.f ? vx : (__expf(vx) - 1.f);
                    vy = vy > 0.f ? vy : (__expf(vy) - 1.f);
                    vz = vz > 0.f ? vz : (__expf(vz) - 1.f);
                    vw = vw > 0.f ? vw : (__expf(vw) - 1.f);
                    *(uint32_t*)(s_o1 + r0 * 136 + col) = pack_h2(vx, vy);
                    *(uint32_t*)(s_o1 + (r0 + 8) * 136 + col) = pack_h2(vz, vw);
                }
            }
        }
        __syncthreads();                                 // S2: o1 visible

        // GEMM2 partial (1-pass): acc2 += o1_head @ W2[head]
        {
            uint32_t aoff = (uint32_t)((wm * 16 + (lane & 15)) * 272 + (lane >> 4) * 16);
#pragma unroll
            for (int kk = 0; kk < 8; kk++) {
                uint32_t Ah[4];
                LDSM_X4(Ah[0], Ah[1], Ah[2], Ah[3], sbO1 + aoff + kk * 32);
                int base = ((h * 8 + kk) * 16 + wn * 8) * 32 + lane;
#pragma unroll
                for (int i = 0; i < 8; i++) {
                    uint2 bw = __ldg(&g_w2pk[base + i * 32]);
                    MMAF16(acc2[i], Ah, bw.x, bw.y);
                }
            }
        }
    }

    // ---------- h2 write (fp32, X region) + GAT2 score partials from registers ----------
    {
        float p1s = 0.f, p1d = 0.f, p2s = 0.f, p2d = 0.f;
#pragma unroll
        for (int i = 0; i < 8; i++) {
            int col = wn * 64 + i * 8 + gc;
            s_h2[r0 * 132 + col]           = acc2[i][0];
            s_h2[r0 * 132 + col + 1]       = acc2[i][1];
            s_h2[(r0 + 8) * 132 + col]     = acc2[i][2];
            s_h2[(r0 + 8) * 132 + col + 1] = acc2[i][3];
            float as0 = __ldg(&a_src2[col]), as1 = __ldg(&a_src2[col + 1]);
            float ad0 = __ldg(&a_dst2[col]), ad1 = __ldg(&a_dst2[col + 1]);
            p1s += acc2[i][0] * as0 + acc2[i][1] * as1;
            p1d += acc2[i][0] * ad0 + acc2[i][1] * ad1;
            p2s += acc2[i][2] * as0 + acc2[i][3] * as1;
            p2d += acc2[i][2] * ad0 + acc2[i][3] * ad1;
        }
        atomicAdd(&s_s2[r0], p1s);
        atomicAdd(&s_s2[64 + r0], p1d);
        atomicAdd(&s_s2[r0 + 8], p2s);
        atomicAdd(&s_s2[64 + r0 + 8], p2d);
    }
    __syncthreads();

    // ---------- GAT2 softmax (serial per target) ----------
    if (t < 64) {
        int tt = t;
        int k0 = s_startc[tt], k1 = s_startc[tt + 1];
        float sd = s_s2[64 + tt];
        float mx = -1e30f;
        for (int k = k0; k < k1; k++) {
            float sc = s_s2[s_esrc[k]] + sd;
            sc = sc > 0.f ? sc : 0.2f * sc;
            s_aprob[k] = sc;
            mx = fmaxf(mx, sc);
        }
        float sum = 0.f;
        for (int k = k0; k < k1; k++) {
            float p = __expf(s_aprob[k] - mx);
            s_aprob[k] = p;
            sum += p;
        }
        float inv = 1.f / (sum + 1e-16f);
        for (int k = k0; k < k1; k++) s_aprob[k] *= inv;
    }
    __syncthreads();

    // ---------- pooled GAT2: q[src] = sum_t alpha2[t][src]; g = q·h2/64 + b2 ----------
    if (t < 192) atomicAdd(&s_q[s_esrc[t]], s_aprob[t]);
    __syncthreads();
    if (t < 128) {
        float a = 0.f;
#pragma unroll 8
        for (int src = 0; src < 64; src++)
            a = fmaf(s_q[src], s_h2[src * 132 + t], a);
        s_g[t] = a * (1.0f / 64.0f) + __ldg(&b2[t]);
    }
    __syncthreads();

    // ---------- classifier ----------
    if (t < 64) {
        float a = __ldg(&bc1[t]);
#pragma unroll 8
        for (int d = 0; d < 128; d++) a = fmaf(s_g[d], __ldg(&Wc1[d * 64 + t]), a);
        s_hc[t] = a > 0.f ? a : 0.01f * a;
    }
    __syncthreads();
    if (t < 16) {
        float a = __ldg(&bc2[t]);
#pragma unroll 8
        for (int j = 0; j < 64; j++) a = fmaf(s_hc[j], __ldg(&Wc2[j * 16 + t]), a);
        outp[(size_t)b * 16 + t] = a;
    }
}

// ---------------- launch ----------------
extern "C" void kernel_launch(void* const* d_in, const int* in_sizes, int n_in,
                              void* d_out, int out_size)
{
    const float* emb         = (const float*)d_in[0];
    const int*   edge_index  = (const int*)d_in[1];
    const float* W_align     = (const float*)d_in[3];
    const float* b_align     = (const float*)d_in[4];
    const float* gate_logits = (const float*)d_in[5];
    const float* W1          = (const float*)d_in[6];
    const float* a_src1      = (const float*)d_in[7];
    const float* a_dst1      = (const float*)d_in[8];
    const float* b1          = (const float*)d_in[9];
    const float* W2          = (const float*)d_in[10];
    const float* a_src2      = (const float*)d_in[11];
    const float* a_dst2      = (const float*)d_in[12];
    const float* b2          = (const float*)d_in[13];
    const float* Wc1         = (const float*)d_in[14];
    const float* bc1         = (const float*)d_in[15];
    const float* Wc2         = (const float*)d_in[16];
    const float* bc2         = (const float*)d_in[17];
    float* out = (float*)d_out;

    cudaFuncSetAttribute(mega_kernel, cudaFuncAttributeMaxDynamicSharedMemorySize, MG_DYN);

    float* gate_out = (out_size >= 64) ? (out + (out_size - 64)) : nullptr;

    // 1) prep: weight fragments + score vectors + gate (164 blocks)
    prep_kernel<<<164, 256>>>(W_align, W1, W2, b_align,
                              a_src1, a_dst1, gate_logits, gate_out);

    // 2) fused per-graph pipeline (emb staged in-kernel)
    mega_kernel<<<B_GRAPHS, 256, MG_DYN>>>(
        edge_index, gate_logits, emb,
        b1, a_src2, a_dst2, b2,
        Wc1, bc1, Wc2, bc2, out);
}

// round 14
// speedup vs baseline: 1.3133x; 1.2235x over previous
#include <cuda_runtime.h>
#include <cuda_fp16.h>
#include <math.h>
#include <cstdint>

// ---------------- problem constants ----------------
#define B_GRAPHS 2048
#define F_NODES  64
#define D_IN     32
#define HDIM     128
#define HEADS    4
#define NC       16
#define EPG      128
#define N_NODES  (B_GRAPHS * F_NODES)        // 131072
#define E_EDGES  (B_GRAPHS * EPG)            // 262144

// ---------------- device-global scratch ----------------
// paired B-fragments: uint4 = fragments (2*i4, 2*i4+1) for one lane
__device__ uint4 g_w1pk4[2 * 32 * 32];        // W1' B-frags [ks(2)][gnt-pair(32)][lane]
__device__ float g_c1[512];                   // b_align @ W1
__device__ uint4 g_w2pk4[32 * 8 * 32];        // W2^T B-frags [ks(32)][gnt-pair(8)][lane]
__device__ float g_w1a[8 * 32];               // [sel*4+h][32] = Wa@(W1@a)
__device__ float g_c1a[8];                    // c1 · a

// ---------------- PTX helpers (sm_80+; no tcgen05 — ptxas targets compute_103) ----------------
__device__ __forceinline__ uint32_t smem_to_u32(const void* p) {
    uint32_t a;
    asm("{ .reg .u64 tmp; cvta.to.shared.u64 tmp, %1; cvt.u32.u64 %0, tmp; }" : "=r"(a) : "l"(p));
    return a;
}
#define LDSM_X4(r0, r1, r2, r3, addr) \
    asm volatile("ldmatrix.sync.aligned.m8n8.x4.shared.b16 {%0,%1,%2,%3}, [%4];" \
                 : "=r"(r0), "=r"(r1), "=r"(r2), "=r"(r3) : "r"(addr))
#define LDSM_X4T(r0, r1, r2, r3, addr) \
    asm volatile("ldmatrix.sync.aligned.m8n8.x4.trans.shared.b16 {%0,%1,%2,%3}, [%4];" \
                 : "=r"(r0), "=r"(r1), "=r"(r2), "=r"(r3) : "r"(addr))

#define MMAF16(d, a, b0, b1) \
    asm volatile("mma.sync.aligned.m16n8k16.row.col.f32.f16.f16.f32 " \
                 "{%0,%1,%2,%3}, {%4,%5,%6,%7}, {%8,%9}, {%0,%1,%2,%3};" \
                 : "+f"((d)[0]), "+f"((d)[1]), "+f"((d)[2]), "+f"((d)[3]) \
                 : "r"((a)[0]), "r"((a)[1]), "r"((a)[2]), "r"((a)[3]), "r"(b0), "r"(b1))

__device__ __forceinline__ uint32_t pack_h2(float a, float b) {
    __half2 v = __halves2half2(__float2half_rn(a), __float2half_rn(b));
    return *(uint32_t*)&v;
}
__device__ __forceinline__ void split_pair_h(float a, float b, uint32_t& hi, uint32_t& lo) {
    __half ha = __float2half_rn(a), hb = __float2half_rn(b);
    __half2 H = __halves2half2(ha, hb);
    __half2 L = __halves2half2(__float2half_rn(a - __half2float(ha)),
                               __float2half_rn(b - __half2float(hb)));
    hi = *(uint32_t*)&H;
    lo = *(uint32_t*)&L;
}

// ---------------- prep kernel ----------------
// blocks [0,163): weight frags + c1 + gate | block 163: score vectors (vectorized)
__global__ __launch_bounds__(256) void prep_kernel(
    const float* __restrict__ Wa, const float* __restrict__ W1,
    const float* __restrict__ W2, const float* __restrict__ b_align,
    const float* __restrict__ a_src1, const float* __restrict__ a_dst1,
    const float* __restrict__ gl, float* __restrict__ gate_out)
{
    int bid = blockIdx.x, t = threadIdx.x;
    if (bid < 163) {
        int gid = bid * 256 + t;
        if (gid < 8192) {
            int reg = gid & 1, lane = (gid >> 1) & 31, gnt = (gid >> 6) & 63, ks = gid >> 12;
            int n = gnt * 8 + (lane >> 2);
            int k = ks * 16 + reg * 8 + (lane & 3) * 2;
            float v0 = 0.f, v1 = 0.f;
#pragma unroll 8
            for (int m = 0; m < 128; m++) {
                v0 = fmaf(Wa[k * 128 + m], W1[m * 512 + n], v0);
                v1 = fmaf(Wa[(k + 1) * 128 + m], W1[m * 512 + n], v1);
            }
            // paired layout: uint2 half (gnt&1) of uint4 at pair (ks*64+gnt)>>1
            int pair = (ks * 64 + gnt) >> 1;
            ((uint2*)g_w1pk4)[(pair * 32 + lane) * 2 + (gnt & 1)] =
                make_uint2(pack_h2(v0, v1) * 0u + pack_h2(v0, v1), 0u) ,
            // NOTE: we need the SECOND word too; write explicitly below
            ((uint2*)g_w1pk4)[(pair * 32 + lane) * 2 + (gnt & 1)] = make_uint2(pack_h2(v0, v1), pack_h2(v0, v1));
            // overwrite with correct pair: b0 = reg0 value? Each gid covers ONE reg (b0 or b1)
            // Correction: each (gnt,lane) fragment is a uint2 {b0,b1} built from reg=0 and reg=1 gids.
            // Write the single 32-bit word for this reg:
            ((uint32_t*)g_w1pk4)[((pair * 32 + lane) * 2 + (gnt & 1)) * 2 + reg] = pack_h2(v0, v1);
        } else if (gid < 40960) {
            int wid = gid - 8192;
            int reg = wid & 1, lane = (wid >> 1) & 31, gnt = (wid >> 6) & 15, ks = wid >> 10;
            int n = gnt * 8 + (lane >> 2);
            int k = ks * 16 + reg * 8 + (lane & 3) * 2;
            int pair = (ks * 16 + gnt) >> 1;
            ((uint32_t*)g_w2pk4)[((pair * 32 + lane) * 2 + (gnt & 1)) * 2 + reg] =
                pack_h2(W2[k * 128 + n], W2[(k + 1) * 128 + n]);
        } else if (gid < 41472) {
            int n = gid - 40960;
            float acc = 0.f;
            const float4* ba = (const float4*)b_align;
#pragma unroll
            for (int m4 = 0; m4 < 32; m4++) {
                float4 bv = __ldg(&ba[m4]);
                acc = fmaf(bv.x, W1[(m4 * 4 + 0) * 512 + n], acc);
                acc = fmaf(bv.y, W1[(m4 * 4 + 1) * 512 + n], acc);
                acc = fmaf(bv.z, W1[(m4 * 4 + 2) * 512 + n], acc);
                acc = fmaf(bv.w, W1[(m4 * 4 + 3) * 512 + n], acc);
            }
            g_c1[n] = acc;
        } else if (gid < 41536) {
            int f = gid - 41472;
            if (gate_out != nullptr) gate_out[f] = 1.0f / (1.0f + expf(-gl[f]));
        }
    } else {
        // score vectors, vectorized float4 loads
        __shared__ float t1[8][128];
        for (int i = 0; i < 4; i++) {
            int e = t * 4 + i;                   // 1024 entries
            int hs = e >> 7, m = e & 127;
            int h = hs & 3, sel = hs >> 2;
            const float4* av = (const float4*)((sel ? a_dst1 : a_src1) + h * 128);
            const float4* wr = (const float4*)(W1 + m * 512 + h * 128);
            float acc = 0.f;
#pragma unroll
            for (int q = 0; q < 32; q++) {
                float4 a4 = __ldg(&av[q]);
                float4 w4 = __ldg(&wr[q]);
                acc += a4.x * w4.x + a4.y * w4.y + a4.z * w4.z + a4.w * w4.w;
            }
            t1[hs][m] = acc;
        }
        __syncthreads();
        {
            int hs = t >> 5, k = t & 31;
            const float4* wa = (const float4*)(Wa + k * 128);
            const float4* tv = (const float4*)t1[hs];
            float acc = 0.f;
#pragma unroll
            for (int q = 0; q < 32; q++) {
                float4 w4 = __ldg(&wa[q]);
                float4 t4 = tv[q];
                acc += w4.x * t4.x + w4.y * t4.y + w4.z * t4.z + w4.w * t4.w;
            }
            g_w1a[t] = acc;
        }
        if (t < 8) {
            const float4* ba = (const float4*)b_align;
            const float4* tv = (const float4*)t1[t];
            float acc = 0.f;
#pragma unroll
            for (int q = 0; q < 32; q++) {
                float4 b4 = __ldg(&ba[q]);
                float4 t4 = tv[q];
                acc += b4.x * t4.x + b4.y * t4.y + b4.z * t4.z + b4.w * t4.w;
            }
            g_c1a[t] = acc;
        }
    }
}

// ---------------- mega kernel (R13 layout) ----------------
// dyn smem (61440 B, occ 3):
//  X [0,33792): loop = h1 fp16 [64][136] (17408) + alpha fp16 [64][72] @17408 (9216); post = h2 fp32 [64][132]
//  o1 fp16 [64][136] @33792 (17408)
//  emb stage hi/lo fp16 [64][40] each @51200/@56320 (10240)
#define MG_ALPHA 17408
#define MG_O1    33792
#define MG_EMB   51200
#define MG_DYN   61440

__global__ __launch_bounds__(256, 3) void mega_kernel(
    const int* __restrict__ eidx, const float* __restrict__ gl,
    const float* __restrict__ emb,
    const float* __restrict__ b1,
    const float* __restrict__ a_src2, const float* __restrict__ a_dst2,
    const float* __restrict__ b2,
    const float* __restrict__ Wc1, const float* __restrict__ bc1,
    const float* __restrict__ Wc2, const float* __restrict__ bc2,
    float* __restrict__ outp)
{
    extern __shared__ __align__(16) char smem[];
    __half* s_h1  = (__half*)smem;                       // stride 136 halves
    __half* s_al  = (__half*)(smem + MG_ALPHA);          // stride 72 halves
    float*  s_h2  = (float*)smem;                        // stride 132 (post-loop)
    __half* s_o1  = (__half*)(smem + MG_O1);             // stride 136 halves
    uint32_t sb    = smem_to_u32(smem);
    uint32_t sbAl  = sb + MG_ALPHA;
    uint32_t sbO1  = sb + MG_O1;
    uint32_t sbEmb = sb + MG_EMB;

    __shared__ int   s_ed[192], s_esrc[192], s_startc[65], s_deg[64], s_cur[64];
    __shared__ float s_sc[2][4][64];
    __shared__ float s_aprob[4 * 192];
    __shared__ float s_s2[128];
    __shared__ float s_q[64], s_g[128], s_hc[64];

    int b = blockIdx.x, t = threadIdx.x, lane = t & 31, w = t >> 5;
    int wm = w >> 1, wn = w & 1;                         // 4 x 2
    int gr = lane >> 2, gc = (lane & 3) * 2;
    int node0 = b * 64;
    int r0 = wm * 16 + gr;

    // ---------- phase 0 ----------
    if (t < 64) { s_deg[t] = 0; s_cur[t] = 0; s_q[t] = 0.f; }
    if (t >= 64 && t < 192) s_s2[t - 64] = 0.f;
    if (t < 192) {
        int src, tt;
        if (t < 128) { src = eidx[b * 128 + t] - node0; tt = eidx[E_EDGES + b * 128 + t] - node0; }
        else         { src = t - 128; tt = src; }
        s_ed[t] = src | (tt << 8);
    }
    {
        uint32_t* az = (uint32_t*)(smem + MG_ALPHA);
#pragma unroll
        for (int i = 0; i < 9; i++) az[t + i * 256] = 0u;
    }
    // stage emb as hi/lo fp16 (80 B rows)
    {
        __half* eh = (__half*)(smem + MG_EMB);
        __half* el = eh + 64 * 40;
#pragma unroll
        for (int i = 0; i < 4; i++) {
            int f = t * 4 + i;
            int row = f >> 4, p = f & 15;
            float2 v = *(const float2*)(emb + (size_t)(node0 + row) * 32 + p * 2);
            uint32_t hi, lo;
            split_pair_h(v.x, v.y, hi, lo);
            *(uint32_t*)(eh + row * 40 + p * 2) = hi;
            *(uint32_t*)(el + row * 40 + p * 2) = lo;
        }
    }
    // GAT1 scores via precomputed 32-vectors
    {
        int row = t & 63, sel = (t >> 6) & 1, hp = t >> 7;
        const float4* erow = (const float4*)(emb + (size_t)(node0 + row) * 32);
        float4 e0 = __ldg(erow), e1 = __ldg(erow + 1), e2 = __ldg(erow + 2), e3 = __ldg(erow + 3);
        float4 e4 = __ldg(erow + 4), e5 = __ldg(erow + 5), e6 = __ldg(erow + 6), e7 = __ldg(erow + 7);
        float gate = 1.0f / (1.0f + __expf(-__ldg(&gl[row])));
#pragma unroll
        for (int hh = 0; hh < 2; hh++) {
            int h = hp * 2 + hh, hs = sel * 4 + h;
            const float4* wv = (const float4*)(g_w1a + hs * 32);
            float s = __ldg(&g_c1a[hs]);
            float4 w0 = __ldg(wv), w1v = __ldg(wv + 1), w2v = __ldg(wv + 2), w3v = __ldg(wv + 3);
            float4 w4 = __ldg(wv + 4), w5 = __ldg(wv + 5), w6 = __ldg(wv + 6), w7 = __ldg(wv + 7);
            s += e0.x*w0.x + e0.y*w0.y + e0.z*w0.z + e0.w*w0.w;
            s += e1.x*w1v.x + e1.y*w1v.y + e1.z*w1v.z + e1.w*w1v.w;
            s += e2.x*w2v.x + e2.y*w2v.y + e2.z*w2v.z + e2.w*w2v.w;
            s += e3.x*w3v.x + e3.y*w3v.y + e3.z*w3v.z + e3.w*w3v.w;
            s += e4.x*w4.x + e4.y*w4.y + e4.z*w4.z + e4.w*w4.w;
            s += e5.x*w5.x + e5.y*w5.y + e5.z*w5.z + e5.w*w5.w;
            s += e6.x*w6.x + e6.y*w6.y + e6.z*w6.z + e6.w*w6.w;
            s += e7.x*w7.x + e7.y*w7.y + e7.z*w7.z + e7.w*w7.w;
            s_sc[sel][h][row] = gate * s;
        }
    }
    float gate0 = 1.0f / (1.0f + __expf(-__ldg(&gl[r0])));
    float gate1 = 1.0f / (1.0f + __expf(-__ldg(&gl[r0 + 8])));
    __syncthreads();
    if (t < 192) atomicAdd(&s_deg[s_ed[t] >> 8], 1);
    __syncthreads();
    if (w == 0) {
        int v0 = s_deg[lane * 2], v1 = s_deg[lane * 2 + 1];
        int p = v0 + v1, run = p;
#pragma unroll
        for (int off = 1; off < 32; off <<= 1) {
            int n = __shfl_up_sync(0xffffffffu, run, off);
            if (lane >= off) run += n;
        }
        s_startc[lane * 2] = run - p;
        s_startc[lane * 2 + 1] = run - p + v0;
        if (lane == 31) s_startc[64] = run;
    }
    __syncthreads();
    if (t < 192) {
        int tt = s_ed[t] >> 8, src = s_ed[t] & 255;
        int pos = atomicAdd(&s_cur[tt], 1);
        s_esrc[s_startc[tt] + pos] = src;
    }
    __syncthreads();

    // ---------- GAT1 softmax, all 4 heads ----------
    {
        int h = t >> 6, tt = t & 63;
        int k0 = s_startc[tt], k1 = s_startc[tt + 1];
        float sd = s_sc[1][h][tt];
        float* ap = s_aprob + h * 192;
        float mx = -1e30f;
        for (int k = k0; k < k1; k++) {
            float sc = s_sc[0][h][s_esrc[k]] + sd;
            sc = sc > 0.f ? sc : 0.2f * sc;
            ap[k] = sc;
            mx = fmaxf(mx, sc);
        }
        float sum = 0.f;
        for (int k = k0; k < k1; k++) {
            float p = __expf(ap[k] - mx);
            ap[k] = p;
            sum += p;
        }
        float inv = 1.f / (sum + 1e-16f);
        for (int k = k0; k < k1; k++) ap[k] *= inv;
    }
    __syncthreads();

    float acc2[8][4] = {};

    // ---------- head loop ----------
    uint32_t aEmbH = sbEmb + (uint32_t)((wm * 16 + (lane & 15)) * 80 + (lane >> 4) * 16);
    uint32_t aEmbL = aEmbH + 5120;

    for (int h = 0; h < HEADS; h++) {
        int hoff = h * 128;

        float acc1[8][4] = {};
#pragma unroll
        for (int ks = 0; ks < 2; ks++) {
            uint32_t Ah[4], Al[4];
            LDSM_X4(Ah[0], Ah[1], Ah[2], Ah[3], aEmbH + ks * 32);
            LDSM_X4(Al[0], Al[1], Al[2], Al[3], aEmbL + ks * 32);
            int pbase = ((ks * 64 + h * 16 + wn * 8) >> 1) * 32 + lane;
#pragma unroll
            for (int i4 = 0; i4 < 4; i4++) {
                uint4 bw = __ldg(&g_w1pk4[pbase + i4 * 32]);
                MMAF16(acc1[i4 * 2],     Ah, bw.x, bw.y);
                MMAF16(acc1[i4 * 2],     Al, bw.x, bw.y);
                MMAF16(acc1[i4 * 2 + 1], Ah, bw.z, bw.w);
                MMAF16(acc1[i4 * 2 + 1], Al, bw.z, bw.w);
            }
        }
        // epilogue: h1 = gate*(acc + c1) -> fp16 smem
#pragma unroll
        for (int i = 0; i < 8; i++) {
            int col = wn * 64 + i * 8 + gc;
            float c0 = __ldg(&g_c1[hoff + col]), c1v = __ldg(&g_c1[hoff + col + 1]);
            *(uint32_t*)(s_h1 + r0 * 136 + col) =
                pack_h2(gate0 * (acc1[i][0] + c0), gate0 * (acc1[i][1] + c1v));
            *(uint32_t*)(s_h1 + (r0 + 8) * 136 + col) =
                pack_h2(gate1 * (acc1[i][2] + c0), gate1 * (acc1[i][3] + c1v));
        }
        // alpha build
        if (t < 64) {
            int tt = t;
            int k0 = s_startc[tt], k1 = s_startc[tt + 1];
            const float* ap = s_aprob + h * 192;
            __half* row = s_al + tt * 72;
            for (int k = k0; k < k1; k++) row[s_esrc[k]] = __float2half_rn(0.f);
            for (int k = k0; k < k1; k++) {
                int s = s_esrc[k];
                row[s] = __float2half_rn(__half2float(row[s]) + ap[k]);
            }
        }
        __syncthreads();                                 // S1

        // agg MMA: o1 = alpha @ h1
        {
            uint32_t aAddr = sbAl + (uint32_t)((wm * 16 + (lane & 15)) * 144 + (lane >> 4) * 16);
#pragma unroll
            for (int nh = 0; nh < 2; nh++) {
                int n0 = wn * 64 + nh * 32;
                uint32_t bAddr = sb + (uint32_t)((lane & 15) * 272 + (n0 + (lane >> 4) * 8) * 2);
                float ag[4][4] = {};
#pragma unroll
                for (int ks = 0; ks < 4; ks++) {
                    uint32_t A[4], B0[4], B1[4];
                    LDSM_X4(A[0], A[1], A[2], A[3], aAddr + ks * 32);
                    LDSM_X4T(B0[0], B0[1], B0[2], B0[3], bAddr + ks * 4352);
                    LDSM_X4T(B1[0], B1[1], B1[2], B1[3], bAddr + 32 + ks * 4352);
                    MMAF16(ag[0], A, B0[0], B0[1]);
                    MMAF16(ag[1], A, B0[2], B0[3]);
                    MMAF16(ag[2], A, B1[0], B1[1]);
                    MMAF16(ag[3], A, B1[2], B1[3]);
                }
#pragma unroll
                for (int nt = 0; nt < 4; nt++) {
                    int col = n0 + nt * 8 + gc;
                    float b0v = __ldg(&b1[hoff + col]), b1v = __ldg(&b1[hoff + col + 1]);
                    float vx = ag[nt][0] + b0v, vy = ag[nt][1] + b1v;
                    float vz = ag[nt][2] + b0v, vw = ag[nt][3] + b1v;
                    vx = vx > 0.f ? vx : (__expf(vx) - 1.f);
                    vy = vy > 0.f ? vy : (__expf(vy) - 1.f);
                    vz = vz > 0.f ? vz : (__expf(vz) - 1.f);
                    vw = vw > 0.f ? vw : (__expf(vw) - 1.f);
                    *(uint32_t*)(s_o1 + r0 * 136 + col) = pack_h2(vx, vy);
                    *(uint32_t*)(s_o1 + (r0 + 8) * 136 + col) = pack_h2(vz, vw);
                }
            }
        }
        __syncthreads();                                 // S2

        // GEMM2 partial (1-pass): acc2 += o1_head @ W2[head]
        {
            uint32_t aoff = (uint32_t)((wm * 16 + (lane & 15)) * 272 + (lane >> 4) * 16);
#pragma unroll
            for (int kk = 0; kk < 8; kk++) {
                uint32_t Ah[4];
                LDSM_X4(Ah[0], Ah[1], Ah[2], Ah[3], sbO1 + aoff + kk * 32);
                int pbase = (((h * 8 + kk) * 16 + wn * 8) >> 1) * 32 + lane;
#pragma unroll
                for (int i4 = 0; i4 < 4; i4++) {
                    uint4 bw = __ldg(&g_w2pk4[pbase + i4 * 32]);
                    MMAF16(acc2[i4 * 2],     Ah, bw.x, bw.y);
                    MMAF16(acc2[i4 * 2 + 1], Ah, bw.z, bw.w);
                }
            }
        }
    }

    // ---------- h2 write + GAT2 score partials ----------
    {
        float p1s = 0.f, p1d = 0.f, p2s = 0.f, p2d = 0.f;
#pragma unroll
        for (int i = 0; i < 8; i++) {
            int col = wn * 64 + i * 8 + gc;
            s_h2[r0 * 132 + col]           = acc2[i][0];
            s_h2[r0 * 132 + col + 1]       = acc2[i][1];
            s_h2[(r0 + 8) * 132 + col]     = acc2[i][2];
            s_h2[(r0 + 8) * 132 + col + 1] = acc2[i][3];
            float as0 = __ldg(&a_src2[col]), as1 = __ldg(&a_src2[col + 1]);
            float ad0 = __ldg(&a_dst2[col]), ad1 = __ldg(&a_dst2[col + 1]);
            p1s += acc2[i][0] * as0 + acc2[i][1] * as1;
            p1d += acc2[i][0] * ad0 + acc2[i][1] * ad1;
            p2s += acc2[i][2] * as0 + acc2[i][3] * as1;
            p2d += acc2[i][2] * ad0 + acc2[i][3] * ad1;
        }
        atomicAdd(&s_s2[r0], p1s);
        atomicAdd(&s_s2[64 + r0], p1d);
        atomicAdd(&s_s2[r0 + 8], p2s);
        atomicAdd(&s_s2[64 + r0 + 8], p2d);
    }
    __syncthreads();

    // ---------- GAT2 softmax ----------
    if (t < 64) {
        int tt = t;
        int k0 = s_startc[tt], k1 = s_startc[tt + 1];
        float sd = s_s2[64 + tt];
        float mx = -1e30f;
        for (int k = k0; k < k1; k++) {
            float sc = s_s2[s_esrc[k]] + sd;
            sc = sc > 0.f ? sc : 0.2f * sc;
            s_aprob[k] = sc;
            mx = fmaxf(mx, sc);
        }
        float sum = 0.f;
        for (int k = k0; k < k1; k++) {
            float p = __expf(s_aprob[k] - mx);
            s_aprob[k] = p;
            sum += p;
        }
        float inv = 1.f / (sum + 1e-16f);
        for (int k = k0; k < k1; k++) s_aprob[k] *= inv;
    }
    __syncthreads();

    // ---------- pooled GAT2 ----------
    if (t < 192) atomicAdd(&s_q[s_esrc[t]], s_aprob[t]);
    __syncthreads();
    if (t < 128) {
        float a = 0.f;
#pragma unroll 8
        for (int src = 0; src < 64; src++)
            a = fmaf(s_q[src], s_h2[src * 132 + t], a);
        s_g[t] = a * (1.0f / 64.0f) + __ldg(&b2[t]);
    }
    __syncthreads();

    // ---------- classifier ----------
    if (t < 64) {
        float a = __ldg(&bc1[t]);
#pragma unroll 8
        for (int d = 0; d < 128; d++) a = fmaf(s_g[d], __ldg(&Wc1[d * 64 + t]), a);
        s_hc[t] = a > 0.f ? a : 0.01f * a;
    }
    __syncthreads();
    if (t < 16) {
        float a = __ldg(&bc2[t]);
#pragma unroll 8
        for (int j = 0; j < 64; j++) a = fmaf(s_hc[j], __ldg(&Wc2[j * 16 + t]), a);
        outp[(size_t)b * 16 + t] = a;
    }
}

// ---------------- launch ----------------
extern "C" void kernel_launch(void* const* d_in, const int* in_sizes, int n_in,
                              void* d_out, int out_size)
{
    const float* emb         = (const float*)d_in[0];
    const int*   edge_index  = (const int*)d_in[1];
    const float* W_align     = (const float*)d_in[3];
    const float* b_align     = (const float*)d_in[4];
    const float* gate_logits = (const float*)d_in[5];
    const float* W1          = (const float*)d_in[6];
    const float* a_src1      = (const float*)d_in[7];
    const float* a_dst1      = (const float*)d_in[8];
    const float* b1          = (const float*)d_in[9];
    const float* W2          = (const float*)d_in[10];
    const float* a_src2      = (const float*)d_in[11];
    const float* a_dst2      = (const float*)d_in[12];
    const float* b2          = (const float*)d_in[13];
    const float* Wc1         = (const float*)d_in[14];
    const float* bc1         = (const float*)d_in[15];
    const float* Wc2         = (const float*)d_in[16];
    const float* bc2         = (const float*)d_in[17];
    float* out = (float*)d_out;

    cudaFuncSetAttribute(mega_kernel, cudaFuncAttributeMaxDynamicSharedMemorySize, MG_DYN);

    float* gate_out = (out_size >= 64) ? (out + (out_size - 64)) : nullptr;

    prep_kernel<<<164, 256>>>(W_align, W1, W2, b_align,
                              a_src1, a_dst1, gate_logits, gate_out);

    mega_kernel<<<B_GRAPHS, 256, MG_DYN>>>(
        edge_index, gate_logits, emb,
        b1, a_src2, a_dst2, b2,
        Wc1, bc1, Wc2, bc2, out);
}